// round 7
// baseline (speedup 1.0000x reference)
#include <cuda_runtime.h>
#include <cstdint>

#define NN      131071
#define NSTEPS  335
#define QLB     1e-4f
#define FULLM   0xFFFFFFFFu

// doorbells: flag(high 32) | float bits(low 32), one word per (step, node)
__device__ unsigned long long g1[NSTEPS * 8192];  // level-3 roots
__device__ unsigned long long g2[NSTEPS * 512];   // level-7 roots
__device__ unsigned long long g3[NSTEPS * 32];    // level-11 roots
__device__ unsigned long long g4[NSTEPS * 2];     // level-15 roots

__global__ void init_kernel() {
    int i = blockIdx.x * blockDim.x + threadIdx.x;
    if (i < NSTEPS * 8192) g1[i] = 0ull;
    if (i < NSTEPS * 512)  g2[i] = 0ull;
    if (i < NSTEPS * 32)   g3[i] = 0ull;
    if (i < NSTEPS * 2)    g4[i] = 0ull;
}

__device__ __forceinline__ float ex2f(float x) {
    float r; asm("ex2.approx.ftz.f32 %0, %1;" : "=f"(r) : "f"(x)); return r;
}

struct NodeC {
    float lgA, pexp, inv_ns, wet_c, tw, ssx2, a1len, a2len;
};

__device__ __forceinline__ NodeC make_node(int g,
    const float* __restrict__ nr,  const float* __restrict__ qsr,
    const float* __restrict__ len, const float* __restrict__ slope,
    const float* __restrict__ twp, const float* __restrict__ ssp,
    const float* __restrict__ xp)
{
    NodeC c;
    float n  = fmaf(nr[g], 0.34f, 0.01f);
    float qs = 3.0f * qsr[g];
    float s0 = fmaxf(slope[g], 1e-4f);
    float sq = sqrtf(s0);
    float den = fmaf(21.0f, sq, 1e-8f);
    c.lgA    = __log2f(n * (qs + 1.0f) / den);
    c.pexp   = 3.0f / fmaf(3.0f, qs, 5.0f);
    c.inv_ns = sq / n;
    float ssv = ssp[g];
    c.wet_c  = 2.0f * sqrtf(fmaf(ssv, ssv, 1.0f));
    c.tw     = twp[g];
    c.ssx2   = 2.0f * ssv;
    float L  = len[g];
    float xv = xp[g];
    c.a1len = 2.0f * (1.0f - xv) * L;
    c.a2len = 2.0f * xv * L;
    return c;
}

// dv = DT*(5/3)*v_clip = 6000*v_clip; r = 1/(dv+a1len);
// c1=(dv-a2len)r; c2=(dv+a2len)r; c4=2dv*r; c3=1-c4
__device__ __forceinline__ void phase_a(const NodeC& c, float q, float it, float qpc,
                                        float& b, float& c1)
{
    float depth  = fmaxf(ex2f(c.pexp * (__log2f(q) + c.lgA)), 0.01f);
    float bottom = fmaxf(fmaf(-c.ssx2, depth, c.tw), 0.1f);
    float area   = (c.tw + bottom) * (0.5f * depth);
    float wetted = fmaf(depth, c.wet_c, bottom);
    float v      = c.inv_ns * ex2f(0.66666668f * (__log2f(area) - __log2f(wetted)));
    v = fminf(fmaxf(v, 0.3f), 15.0f);
    float dv = 6000.0f * v;
    float r  = __fdividef(1.0f, dv + c.a1len);
    c1       = (dv - c.a2len) * r;
    float c2 = (dv + c.a2len) * r;
    float c4 = (2.0f * dv) * r;
    float c3 = 1.0f - c4;
    b = fmaf(c2, it, fmaf(c3, q, c4 * qpc));
}

// 4-level slabs. T1: levels 0-3, TWO subtrees per warp (halves: lanes 0-14 / 16-30).
// T2: levels 4-7 (512 warps), T3: 8-11 (32), T4: 12-15 (2), T5: level 16 (1).
// T2-T5: 15 (or 1) nodes on low lanes, 16 (or 2) pollers on lanes 16+.
__global__ void __launch_bounds__(32)
route_kernel(const float* __restrict__ qp,
             const float* __restrict__ nr,  const float* __restrict__ qsr,
             const float* __restrict__ len, const float* __restrict__ slope,
             const float* __restrict__ twp, const float* __restrict__ ssp,
             const float* __restrict__ xp,  float* __restrict__ out)
{
    const int w    = blockIdx.x;          // 0..4642
    const int lane = threadIdx.x;

    int tier, sub;
    if      (w >= 547) { tier = 1; sub = w - 547; }   // 4096
    else if (w >= 35)  { tier = 2; sub = w - 35;  }   // 512
    else if (w >= 3)   { tier = 3; sub = w - 3;   }   // 32
    else if (w >= 1)   { tier = 4; sub = w - 1;   }   // 2
    else               { tier = 5; sub = 0;       }   // 1

    bool is_node = false, is_poll = false, has_it = true;
    int  gid = 0, sweepd = 99;
    int  sA = 0, sB = 1;
    unsigned long long* pollp = 0; int pollstride = 0;
    unsigned long long* pubp  = 0; int pubstride  = 0;
    bool do_pub = false;

    if (tier == 1) {
        const int half = lane >> 4, ll = lane & 15;
        if (ll < 15) {
            is_node = true;
            int dh = 31 - __clz(ll + 1);              // 0..3; dh==3 are leaves (level 0)
            int j  = ll + 1 - (1 << dh);
            int r  = 2 * sub + half;                  // level-3 root index
            gid = 131072 - (1 << (14 + dh)) + (r << dh) + j;
            if (dh == 3) has_it = false; else sweepd = dh;
        }
        sA = min(2 * ll + 1, 15) + (half << 4);
        sB = min(2 * ll + 2, 15) + (half << 4);
        do_pub = (ll == 0) && is_node;
        pubp = g1 + 2 * sub + half; pubstride = 8192;
    } else {
        const int rl    = (tier == 2) ? 7 : (tier == 3) ? 11 : (tier == 4) ? 15 : 16;
        const int nnode = (tier == 5) ? 1 : 15;
        const int npoll = (tier == 5) ? 2 : 16;
        if (lane < nnode) {
            is_node = true;
            int dh = 31 - __clz(lane + 1);            // 0..3
            int j  = lane + 1 - (1 << dh);
            gid = 131072 - (1 << (17 - rl + dh)) + (sub << dh) + j;
            sweepd = dh;
        }
        is_poll = (lane >= 16) && (lane < 16 + npoll);
        if (tier == 5)                      { sA = 16; sB = 17; }
        else if (lane >= 7 && lane <= 14)   { sA = 2 * lane + 2; sB = 2 * lane + 3; }
        else                                { sA = min(2 * lane + 1, 31); sB = min(2 * lane + 2, 31); }
        const int c = lane - 16;
        if      (tier == 2) { pollp = g1 + sub * 16 + c; pollstride = 8192; pubp = g2 + sub; pubstride = 512; }
        else if (tier == 3) { pollp = g2 + sub * 16 + c; pollstride = 512;  pubp = g3 + sub; pubstride = 32;  }
        else if (tier == 4) { pollp = g3 + sub * 16 + c; pollstride = 32;   pubp = g4 + sub; pubstride = 2;   }
        else                { pollp = g4 + c;            pollstride = 2;    }
        do_pub = (tier != 5) && (lane == 0);
    }

    NodeC cN;
    float cq = 0.0f, qnext = 0.0f;
    if (is_node) {
        cN = make_node(gid, nr, qsr, len, slope, twp, ssp, xp);
        cq = qp[gid];                                  // q0 raw (no clamp)
        qnext = fmaxf(cq, QLB);                        // qpc for step 0
    }
    if (is_poll) {
        const int c = lane - 16;
        int cgid;
        if      (tier == 2) cgid = 131072 - (1 << 14) + sub * 16 + c;   // level 3
        else if (tier == 3) cgid = 131072 - (1 << 10) + sub * 16 + c;   // level 7
        else if (tier == 4) cgid = 131072 - (1 << 6)  + sub * 16 + c;   // level 11
        else                cgid = 131072 - 4 + c;                      // level 15
        cq = qp[cgid];                                 // child q0 raw
    }
    if (tier == 5 && lane == 0) out[0] = fmaxf(qp[NN - 1], QLB);

    for (int t = 0; t < NSTEPS; ++t) {
        float qpc = qnext;
        if (is_node) {                                 // prefetch next step's q_prime
            int tn = (t + 1 < NSTEPS) ? t + 1 : t;
            qnext = fmaxf(__ldg(qp + (size_t)tn * NN + gid), QLB);
        }
        // i_t from children's carry registers (previous-step q)
        float itA = __shfl_sync(FULLM, cq, sA);
        float itB = __shfl_sync(FULLM, cq, sB);
        float b = 0.0f, c1 = 0.0f;
        if (is_node) {
            float it = has_it ? (itA + itB) : 0.0f;
            phase_a(cN, cq, it, qpc, b, c1);
        }
        if (is_poll) {                                 // fetch this step's child root (raw)
            unsigned long long v;
            do {
                asm volatile("ld.acquire.gpu.global.b64 %0, [%1];"
                             : "=l"(v) : "l"(pollp) : "memory");
            } while ((v >> 32) == 0ull);
            b = __uint_as_float((unsigned)v);
            pollp += pollstride;
        }
        __syncwarp(FULLM);
        // bottom-up sweep on raw values, pure shuffles
        if (tier == 1) {
            #pragma unroll
            for (int d = 2; d >= 0; --d) {
                float bl = __shfl_sync(FULLM, b, sA);
                float br = __shfl_sync(FULLM, b, sB);
                if (sweepd == d) b = fmaf(c1, bl + br, b);
            }
        } else {
            #pragma unroll
            for (int d = 3; d >= 0; --d) {
                float bl = __shfl_sync(FULLM, b, sA);
                float br = __shfl_sync(FULLM, b, sB);
                if (sweepd == d) b = fmaf(c1, bl + br, b);
            }
        }
        if (do_pub) {
            unsigned long long pv = (1ull << 32) | (unsigned long long)__float_as_uint(b);
            asm volatile("st.release.gpu.global.b64 [%0], %1;"
                         :: "l"(pubp), "l"(pv) : "memory");
            pubp += pubstride;
        }
        if (tier == 5 && lane == 0) out[t + 1] = fmaxf(b, QLB);
        cq = fmaxf(b, QLB);                            // carry (nodes) / child carry (pollers)
    }
}

extern "C" void kernel_launch(void* const* d_in, const int* in_sizes, int n_in,
                              void* d_out, int out_size)
{
    const float* qp    = (const float*)d_in[0];
    const float* nr    = (const float*)d_in[1];
    const float* qsr   = (const float*)d_in[2];
    const float* len   = (const float*)d_in[3];
    const float* slope = (const float*)d_in[4];
    const float* twp   = (const float*)d_in[5];
    const float* ssp   = (const float*)d_in[6];
    const float* xp    = (const float*)d_in[7];
    float* out = (float*)d_out;

    init_kernel<<<(NSTEPS * 8192 + 255) / 256, 256>>>();
    route_kernel<<<4643, 32>>>(qp, nr, qsr, len, slope, twp, ssp, xp, out);
}